// round 14
// baseline (speedup 1.0000x reference)
#include <cuda_runtime.h>
#include <cuda_bf16.h>
#include <cstdint>

// ---------------- problem constants ----------------
#define NMAX 50000
#define EMAX 600000
#define GMAX 256
#define DH 128

// ---------------- device scratch ----------------
// g_deg / g_cursor rely on static zero-init at load; pool_div restores them to
// zero at the end of every call, so the precondition holds for all replays.
__device__ float g_agg[(size_t)NMAX * DH];
__device__ float g_hA [(size_t)NMAX * DH];
__device__ float g_hB [(size_t)NMAX * DH];
__device__ unsigned short g_xbf[(size_t)NMAX * 64];   // bf16 copy of x
__device__ unsigned short g_hbf[(size_t)NMAX * DH];   // bf16 copy of current h
__device__ int   g_deg[NMAX];
__device__ int   g_rowptr[NMAX + 1];
__device__ int   g_cursor[NMAX];
__device__ int   g_srcs[EMAX];
__device__ float g_gcnt[GMAX];
// pre-split bf16 hi/lo weight images, padded [n][2K+8] layout
__device__ unsigned short g_Bimg[167168];

__device__ __forceinline__ float bfbits2f_lo(uint32_t u) {   // lower ushort
    return __uint_as_float(u << 16);
}
__device__ __forceinline__ float bfbits2f_hi(uint32_t u) {   // upper ushort
    return __uint_as_float(u & 0xFFFF0000u);
}
__device__ __forceinline__ uint32_t pack_bf2(float x, float y) {
    __nv_bfloat16 hx = __float2bfloat16_rn(x);
    __nv_bfloat16 hy = __float2bfloat16_rn(y);
    return ((uint32_t)__bfloat16_as_ushort(hy) << 16) | __bfloat16_as_ushort(hx);
}

// ---------------- setup: zero out/gcnt + build 3 weight images ----------
__device__ __forceinline__ void prep_B_elem(const float* Wl, const float* Wr,
                                            unsigned short* img, int chunks, int t) {
    int strideB = chunks * 128 + 8;
    int Ktot    = chunks * 64;
    int nn = t / strideB;
    int kk = t - nn * strideB;
    if (kk < Ktot) {
        int half = chunks * 32;
        const float* W; int k;
        if (kk < half) { W = Wl; k = kk; } else { W = Wr; k = kk - half; }
        float v = W[(size_t)k * 128 + nn];
        __nv_bfloat16 h = __float2bfloat16_rn(v);
        __nv_bfloat16 l = __float2bfloat16_rn(v - __bfloat162float(h));
        img[nn * strideB + kk]        = __bfloat16_as_ushort(h);
        img[nn * strideB + Ktot + kk] = __bfloat16_as_ushort(l);
    } else if (kk >= 2 * Ktot) {
        img[t] = 0;
    }
}

__global__ void setup_kernel(const float* __restrict__ Wl1, const float* __restrict__ Wr1,
                             const float* __restrict__ Wl2, const float* __restrict__ Wr2,
                             const float* __restrict__ Wl3, const float* __restrict__ Wr3,
                             unsigned short* __restrict__ img,
                             float* __restrict__ out, int G) {
    const int s2 = G * 128;
    const int s3 = s2 + G;
    const int s4 = s3 + 128 * 264;
    const int s5 = s4 + 128 * 520;
    const int s6 = s5 + 128 * 520;
    for (int t = blockIdx.x * blockDim.x + threadIdx.x; t < s6;
         t += gridDim.x * blockDim.x) {
        if (t < s2)       out[t] = 0.0f;
        else if (t < s3)  g_gcnt[t - s2] = 0.0f;
        else if (t < s4)  prep_B_elem(Wl1, Wr1, img,          2, t - s3);
        else if (t < s5)  prep_B_elem(Wl2, Wr2, img + 33792,  4, t - s4);
        else              prep_B_elem(Wl3, Wr3, img + 100352, 4, t - s5);
    }
}

// ---------------- CSR count + fused x->bf16 conversion ----------------
__global__ void count_deg_kernel(const int* __restrict__ dst, int E, int n,
                                 const float* __restrict__ x,
                                 unsigned short* __restrict__ xbf) {
    int t = blockIdx.x * blockDim.x + threadIdx.x;
    int e = 4 * t;
    if (e + 3 < E) {
        int4 d4 = *(const int4*)(dst + e);
        if (d4.x >= 0 && d4.x < n) atomicAdd(&g_deg[d4.x], 1);
        if (d4.y >= 0 && d4.y < n) atomicAdd(&g_deg[d4.y], 1);
        if (d4.z >= 0 && d4.z < n) atomicAdd(&g_deg[d4.z], 1);
        if (d4.w >= 0 && d4.w < n) atomicAdd(&g_deg[d4.w], 1);
    } else {
        for (int k = 0; k < 4; k++) {
            int ee = e + k;
            if (ee < E) {
                int d = dst[ee];
                if (d >= 0 && d < n) atomicAdd(&g_deg[d], 1);
            }
        }
    }
    // fused: convert x (n*64 fp32) to bf16 pairs
    int pairs = n * 32;
    for (int i = t; i < pairs; i += gridDim.x * blockDim.x) {
        float2 v = *(const float2*)(x + 2 * (size_t)i);
        *(uint32_t*)(xbf + 2 * (size_t)i) = pack_bf2(v.x, v.y);
    }
}

// exclusive scan deg -> rowptr; cursor gets base offsets
__global__ void scan_kernel(int n) {
    __shared__ int sh[1024];
    int tid = threadIdx.x;
    int chunk = (n + 1023) / 1024;
    int beg = tid * chunk;
    int end = min(beg + chunk, n);
    int s = 0;
    for (int i = beg; i < end; i++) s += g_deg[i];
    sh[tid] = s;
    __syncthreads();
    for (int off = 1; off < 1024; off <<= 1) {
        int v = (tid >= off) ? sh[tid - off] : 0;
        __syncthreads();
        sh[tid] += v;
        __syncthreads();
    }
    int run = sh[tid] - s;
    for (int i = beg; i < end; i++) {
        g_rowptr[i] = run;
        g_cursor[i] = run;
        run += g_deg[i];
    }
    if (tid == 1023) g_rowptr[n] = sh[1023];
}

__global__ void scatter_kernel(const int* __restrict__ src,
                               const int* __restrict__ dst, int E, int n) {
    int t = blockIdx.x * blockDim.x + threadIdx.x;
    int e = 4 * t;
    if (e + 3 < E) {
        int4 s4 = *(const int4*)(src + e);
        int4 d4 = *(const int4*)(dst + e);
        int p;
        if (d4.x >= 0 && d4.x < n && s4.x >= 0 && s4.x < n) {
            p = atomicAdd(&g_cursor[d4.x], 1); if (p < EMAX) g_srcs[p] = s4.x;
        }
        if (d4.y >= 0 && d4.y < n && s4.y >= 0 && s4.y < n) {
            p = atomicAdd(&g_cursor[d4.y], 1); if (p < EMAX) g_srcs[p] = s4.y;
        }
        if (d4.z >= 0 && d4.z < n && s4.z >= 0 && s4.z < n) {
            p = atomicAdd(&g_cursor[d4.z], 1); if (p < EMAX) g_srcs[p] = s4.z;
        }
        if (d4.w >= 0 && d4.w < n && s4.w >= 0 && s4.w < n) {
            p = atomicAdd(&g_cursor[d4.w], 1); if (p < EMAX) g_srcs[p] = s4.w;
        }
    } else {
        for (int k = 0; k < 4; k++) {
            int ee = e + k;
            if (ee < E) {
                int d = dst[ee];
                int s = src[ee];
                if (d >= 0 && d < n && s >= 0 && s < n) {
                    int p = atomicAdd(&g_cursor[d], 1);
                    if (p < EMAX) g_srcs[p] = s;
                }
            }
        }
    }
}

// ------- mean aggregation from bf16 rows: one warp per node, MLP-4 --------
template <int D>
__global__ void agg_bf_kernel(const unsigned short* __restrict__ xb,
                              float* __restrict__ agg, int n) {
    int gw   = (blockIdx.x * blockDim.x + threadIdx.x) >> 5;
    int lane = threadIdx.x & 31;
    if (gw >= n) return;
    int beg = g_rowptr[gw];
    int end = g_rowptr[gw + 1];
    if (D == 128) {
        // lane covers 4 cols: 4*lane .. 4*lane+3 (uint2 = 4 bf16 = 8B)
        float4 acc = make_float4(0.f, 0.f, 0.f, 0.f);
        int j = beg;
        for (; j + 3 < end; j += 4) {
            int s0 = g_srcs[j],     s1 = g_srcs[j + 1];
            int s2 = g_srcs[j + 2], s3 = g_srcs[j + 3];
            uint2 u0 = __ldg((const uint2*)(xb + (size_t)s0 * D + 4 * lane));
            uint2 u1 = __ldg((const uint2*)(xb + (size_t)s1 * D + 4 * lane));
            uint2 u2 = __ldg((const uint2*)(xb + (size_t)s2 * D + 4 * lane));
            uint2 u3 = __ldg((const uint2*)(xb + (size_t)s3 * D + 4 * lane));
            acc.x += (bfbits2f_lo(u0.x) + bfbits2f_lo(u1.x)) + (bfbits2f_lo(u2.x) + bfbits2f_lo(u3.x));
            acc.y += (bfbits2f_hi(u0.x) + bfbits2f_hi(u1.x)) + (bfbits2f_hi(u2.x) + bfbits2f_hi(u3.x));
            acc.z += (bfbits2f_lo(u0.y) + bfbits2f_lo(u1.y)) + (bfbits2f_lo(u2.y) + bfbits2f_lo(u3.y));
            acc.w += (bfbits2f_hi(u0.y) + bfbits2f_hi(u1.y)) + (bfbits2f_hi(u2.y) + bfbits2f_hi(u3.y));
        }
        for (; j < end; j++) {
            int s0 = g_srcs[j];
            uint2 u0 = __ldg((const uint2*)(xb + (size_t)s0 * D + 4 * lane));
            acc.x += bfbits2f_lo(u0.x); acc.y += bfbits2f_hi(u0.x);
            acc.z += bfbits2f_lo(u0.y); acc.w += bfbits2f_hi(u0.y);
        }
        float inv = 1.0f / fmaxf((float)(end - beg), 1.0f);
        acc.x *= inv; acc.y *= inv; acc.z *= inv; acc.w *= inv;
        *(float4*)(agg + (size_t)gw * D + 4 * lane) = acc;
    } else {
        // D==64: lane covers 2 cols (uint32 = 2 bf16 = 4B)
        float2 acc = make_float2(0.f, 0.f);
        int j = beg;
        for (; j + 3 < end; j += 4) {
            int s0 = g_srcs[j],     s1 = g_srcs[j + 1];
            int s2 = g_srcs[j + 2], s3 = g_srcs[j + 3];
            uint32_t u0 = __ldg((const uint32_t*)(xb + (size_t)s0 * D + 2 * lane));
            uint32_t u1 = __ldg((const uint32_t*)(xb + (size_t)s1 * D + 2 * lane));
            uint32_t u2 = __ldg((const uint32_t*)(xb + (size_t)s2 * D + 2 * lane));
            uint32_t u3 = __ldg((const uint32_t*)(xb + (size_t)s3 * D + 2 * lane));
            acc.x += (bfbits2f_lo(u0) + bfbits2f_lo(u1)) + (bfbits2f_lo(u2) + bfbits2f_lo(u3));
            acc.y += (bfbits2f_hi(u0) + bfbits2f_hi(u1)) + (bfbits2f_hi(u2) + bfbits2f_hi(u3));
        }
        for (; j < end; j++) {
            int s0 = g_srcs[j];
            uint32_t u0 = __ldg((const uint32_t*)(xb + (size_t)s0 * D + 2 * lane));
            acc.x += bfbits2f_lo(u0); acc.y += bfbits2f_hi(u0);
        }
        float inv = 1.0f / fmaxf((float)(end - beg), 1.0f);
        acc.x *= inv; acc.y *= inv;
        *(float2*)(agg + (size_t)gw * D + 2 * lane) = acc;
    }
}

// ---------------- mma / ldmatrix helpers ----------------
__device__ __forceinline__ void mma16816(float* c, const uint32_t* a,
                                         uint32_t b0, uint32_t b1) {
    asm volatile(
        "mma.sync.aligned.m16n8k16.row.col.f32.bf16.bf16.f32 "
        "{%0,%1,%2,%3}, {%4,%5,%6,%7}, {%8,%9}, {%0,%1,%2,%3};"
        : "+f"(c[0]), "+f"(c[1]), "+f"(c[2]), "+f"(c[3])
        : "r"(a[0]), "r"(a[1]), "r"(a[2]), "r"(a[3]), "r"(b0), "r"(b1));
}

__device__ __forceinline__ void ldsm_x4(uint32_t* r, uint32_t addr) {
    asm volatile(
        "ldmatrix.sync.aligned.m8n8.x4.shared.b16 {%0,%1,%2,%3}, [%4];"
        : "=r"(r[0]), "=r"(r[1]), "=r"(r[2]), "=r"(r[3]) : "r"(addr));
}

__device__ __forceinline__ uint32_t smem_u32(const void* p) {
    uint32_t a;
    asm("{ .reg .u64 t; cvta.to.shared.u64 t, %1; cvt.u32.u64 %0, t; }"
        : "=r"(a) : "l"(p));
    return a;
}

// ---------------- persistent tensor-core fused SAGE GEMM ----------------
// out = [agg | x] @ [Wl;Wr] + b (+relu), fp32 via 3-term bf16 split.
// 512 threads, 16 warps (4m x 4n), warp tile 32x32, persistent grid=148.
// WRITE_BF: also emit bf16 copy of the output (aggregation input of next layer).
template <int CHUNKS, bool RELU, bool WRITE_BF>
__global__ __launch_bounds__(512, 1)
void sage_mma(const float* __restrict__ A1, const float* __restrict__ A2,
              const unsigned short* __restrict__ Bimg, const float* __restrict__ bias,
              float* __restrict__ out, unsigned short* __restrict__ outbf,
              int n, int nTiles) {
    constexpr int STRIDEB = CHUNKS * 128 + 8;
    constexpr int KTOT    = CHUNKS * 64;
    constexpr int ASTRIDE = 136;
    constexpr int ASTR32  = CHUNKS * 32;

    extern __shared__ unsigned short sm[];
    unsigned short* As = sm;                    // 128 * 136
    unsigned short* Bs = sm + 128 * ASTRIDE;    // 128 * STRIDEB

    const int tid  = threadIdx.x;
    const int wid  = tid >> 5;
    const int lane = tid & 31;
    const int tq   = lane >> 2;
    const int tr   = lane & 3;
    const int wm   = wid & 3;
    const int wn   = wid >> 2;
    const int g    = lane >> 3;
    const int lr   = lane & 7;

    const uint32_t As_u = smem_u32(As);
    const uint32_t Bs_u = smem_u32(Bs);
    const uint32_t aBase = As_u + (uint32_t)(wm * 32 + (g & 1) * 8 + lr) * (ASTRIDE * 2)
                                + (uint32_t)((g >> 1) * 8) * 2;
    const uint32_t bBase = Bs_u + (uint32_t)(wn * 32 + (g >> 1) * 8 + lr) * (STRIDEB * 2)
                                + (uint32_t)((g & 1) * 8) * 2;

    {
        const float4* bsrc = (const float4*)Bimg;
        float4* bdst = (float4*)Bs;
        constexpr int NV = 128 * STRIDEB * 2 / 16;
        for (int i = tid; i < NV; i += 512) bdst[i] = bsrc[i];
    }

    const int lrow0 = tid >> 5;
    const int lk2   = (tid & 31) * 2;

    float2 v[8];
    auto load_chunk = [&](int m0, int c) {
        const float* src = (c < CHUNKS / 2) ? A1 : A2;
        int kb = (c & (CHUNKS / 2 - 1)) * 64;
#pragma unroll
        for (int i = 0; i < 8; i++) {
            int grow = min(m0 + lrow0 + 16 * i, n - 1);
            v[i] = *(const float2*)(src + (size_t)grow * ASTR32 + kb + lk2);
        }
    };

    int tile = blockIdx.x;
    if (tile < nTiles) load_chunk(tile * 128, 0);

    for (; tile < nTiles; tile += gridDim.x) {
        const int m0 = tile * 128;

        float acc[2][4][4];
#pragma unroll
        for (int a = 0; a < 2; a++)
#pragma unroll
            for (int b = 0; b < 4; b++)
#pragma unroll
                for (int q = 0; q < 4; q++) acc[a][b][q] = 0.0f;

        for (int c = 0; c < CHUNKS; ++c) {
            __syncthreads();

#pragma unroll
            for (int i = 0; i < 8; i++) {
                int row = lrow0 + 16 * i;
                __nv_bfloat16 h0 = __float2bfloat16_rn(v[i].x);
                __nv_bfloat16 h1 = __float2bfloat16_rn(v[i].y);
                __nv_bfloat16 l0 = __float2bfloat16_rn(v[i].x - __bfloat162float(h0));
                __nv_bfloat16 l1 = __float2bfloat16_rn(v[i].y - __bfloat162float(h1));
                uint32_t hp = ((uint32_t)__bfloat16_as_ushort(h1) << 16) | __bfloat16_as_ushort(h0);
                uint32_t lp = ((uint32_t)__bfloat16_as_ushort(l1) << 16) | __bfloat16_as_ushort(l0);
                *(uint32_t*)(As + row * ASTRIDE + lk2)      = hp;
                *(uint32_t*)(As + row * ASTRIDE + 64 + lk2) = lp;
            }

            {
                int nc = c + 1, nt = tile;
                if (nc == CHUNKS) { nc = 0; nt = tile + gridDim.x; }
                if (nt < nTiles) load_chunk(nt * 128, nc);
            }
            __syncthreads();

#pragma unroll
            for (int ks = 0; ks < 4; ks++) {
                uint32_t ah[2][4], al[2][4], bh[2][4], bl[2][4];
#pragma unroll
                for (int ma = 0; ma < 2; ma++) {
                    uint32_t a = aBase + (uint32_t)(ma * 16 * ASTRIDE * 2 + ks * 32);
                    ldsm_x4(ah[ma], a);
                    ldsm_x4(al[ma], a + 128);
                }
#pragma unroll
                for (int p = 0; p < 2; p++) {
                    uint32_t b = bBase + (uint32_t)(p * 16 * STRIDEB * 2 + c * 128 + ks * 32);
                    ldsm_x4(bh[p], b);
                    ldsm_x4(bl[p], b + KTOT * 2);
                }
#pragma unroll
                for (int pass = 0; pass < 3; pass++) {
                    const uint32_t (*Af)[4] = (pass == 1) ? al : ah;
                    const uint32_t (*Bf)[4] = (pass == 2) ? bl : bh;
#pragma unroll
                    for (int ma = 0; ma < 2; ma++)
#pragma unroll
                        for (int p = 0; p < 2; p++) {
                            mma16816(acc[ma][2 * p],     Af[ma], Bf[p][0], Bf[p][1]);
                            mma16816(acc[ma][2 * p + 1], Af[ma], Bf[p][2], Bf[p][3]);
                        }
                }
            }
        }

#pragma unroll
        for (int ma = 0; ma < 2; ma++) {
            int row = m0 + wm * 32 + ma * 16 + tq;
#pragma unroll
            for (int nb = 0; nb < 4; nb++) {
                int col = wn * 32 + nb * 8 + 2 * tr;
                float2 bv = *(const float2*)(bias + col);
                if (row < n) {
                    float2 o;
                    o.x = acc[ma][nb][0] + bv.x;
                    o.y = acc[ma][nb][1] + bv.y;
                    if (RELU) { o.x = fmaxf(o.x, 0.0f); o.y = fmaxf(o.y, 0.0f); }
                    *(float2*)(out + (size_t)row * 128 + col) = o;
                    if (WRITE_BF)
                        *(uint32_t*)(outbf + (size_t)row * 128 + col) = pack_bf2(o.x, o.y);
                }
                if (row + 8 < n) {
                    float2 o;
                    o.x = acc[ma][nb][2] + bv.x;
                    o.y = acc[ma][nb][3] + bv.y;
                    if (RELU) { o.x = fmaxf(o.x, 0.0f); o.y = fmaxf(o.y, 0.0f); }
                    *(float2*)(out + (size_t)(row + 8) * 128 + col) = o;
                    if (WRITE_BF)
                        *(uint32_t*)(outbf + (size_t)(row + 8) * 128 + col) = pack_bf2(o.x, o.y);
                }
            }
        }
    }
}

// ---------------- global mean pool ----------------
__global__ void pool_acc_kernel(const float* __restrict__ h,
                                const int* __restrict__ batch,
                                float* __restrict__ out, int n, int G) {
    const int NPW = 16;
    int gw   = (blockIdx.x * blockDim.x + threadIdx.x) >> 5;
    int lane = threadIdx.x & 31;
    int beg = gw * NPW;
    if (beg >= n) return;
    int end = min(beg + NPW, n);
    float a0 = 0, a1 = 0, a2 = 0, a3 = 0;
    int cur = min(max(batch[beg], 0), G - 1);
    int cnt = 0;
    for (int i = beg; i < end; i++) {
        int b = min(max(batch[i], 0), G - 1);
        if (b != cur) {
            atomicAdd(&out[cur * 128 + lane +  0], a0);
            atomicAdd(&out[cur * 128 + lane + 32], a1);
            atomicAdd(&out[cur * 128 + lane + 64], a2);
            atomicAdd(&out[cur * 128 + lane + 96], a3);
            if (lane == 0) atomicAdd(&g_gcnt[cur], (float)cnt);
            a0 = a1 = a2 = a3 = 0.0f;
            cnt = 0;
            cur = b;
        }
        const float* row = h + (size_t)i * 128;
        a0 += row[lane];      a1 += row[lane + 32];
        a2 += row[lane + 64]; a3 += row[lane + 96];
        cnt++;
    }
    atomicAdd(&out[cur * 128 + lane +  0], a0);
    atomicAdd(&out[cur * 128 + lane + 32], a1);
    atomicAdd(&out[cur * 128 + lane + 64], a2);
    atomicAdd(&out[cur * 128 + lane + 96], a3);
    if (lane == 0) atomicAdd(&g_gcnt[cur], (float)cnt);
}

// final: divide by counts AND restore g_deg/g_cursor to zero for next call
__global__ void pool_div_kernel(float* out, int G, int n) {
    int i = blockIdx.x * blockDim.x + threadIdx.x;
    if (i < G * 128) out[i] /= fmaxf(g_gcnt[i >> 7], 1.0f);
    if (i < n) { g_deg[i] = 0; g_cursor[i] = 0; }
}

// ---------------- launch ----------------
extern "C" void kernel_launch(void* const* d_in, const int* in_sizes, int n_in,
                              void* d_out, int out_size) {
    const float* x     = (const float*)d_in[0];
    const int*   ei    = (const int*)d_in[1];
    const int*   batch = (const int*)d_in[2];
    const float* Wl1 = (const float*)d_in[3];
    const float* bl1 = (const float*)d_in[4];
    const float* Wr1 = (const float*)d_in[5];
    const float* Wl2 = (const float*)d_in[6];
    const float* bl2 = (const float*)d_in[7];
    const float* Wr2 = (const float*)d_in[8];
    const float* Wl3 = (const float*)d_in[9];
    const float* bl3 = (const float*)d_in[10];
    const float* Wr3 = (const float*)d_in[11];
    float* out = (float*)d_out;

    const int n = in_sizes[0] / 64;       // 50000
    const int E = in_sizes[1] / 2;        // 600000
    const int G = out_size / 128;         // 64

    const int* src = ei;
    const int* dst = ei + E;

    void *p_agg, *p_hA, *p_hB, *p_Bimg, *p_xbf, *p_hbf;
    cudaGetSymbolAddress(&p_agg, g_agg);
    cudaGetSymbolAddress(&p_hA, g_hA);
    cudaGetSymbolAddress(&p_hB, g_hB);
    cudaGetSymbolAddress(&p_Bimg, g_Bimg);
    cudaGetSymbolAddress(&p_xbf, g_xbf);
    cudaGetSymbolAddress(&p_hbf, g_hbf);
    float* agg = (float*)p_agg;
    float* hA  = (float*)p_hA;
    float* hB  = (float*)p_hB;
    unsigned short* Bimg = (unsigned short*)p_Bimg;
    unsigned short* xbf  = (unsigned short*)p_xbf;
    unsigned short* hbf  = (unsigned short*)p_hbf;

    const int smem1 = (128 * 136 + 128 * 264) * 2;   // 102400 (CHUNKS=2)
    const int smem2 = (128 * 136 + 128 * 520) * 2;   // 167936 (CHUNKS=4)
    cudaFuncSetAttribute(sage_mma<2, true,  true >, cudaFuncAttributeMaxDynamicSharedMemorySize, smem1);
    cudaFuncSetAttribute(sage_mma<4, true,  true >, cudaFuncAttributeMaxDynamicSharedMemorySize, smem2);
    cudaFuncSetAttribute(sage_mma<4, false, false>, cudaFuncAttributeMaxDynamicSharedMemorySize, smem2);

    const int aggBlocks = (n * 32 + 255) / 256;
    const int nTiles = (n + 127) / 128;
    const int gemmGrid = 148;
    int quads = (E + 3) / 4;

    // ---- CSR build + x->bf16 (g_deg/g_cursor zero by invariant) ----
    count_deg_kernel<<<(quads + 255) / 256, 256>>>(dst, E, n, x, xbf);  // 1
    scan_kernel<<<1, 1024>>>(n);                                         // 2
    scatter_kernel<<<(quads + 255) / 256, 256>>>(src, dst, E, n);        // 3

    // ---- agg layer 1 from bf16 x (launch #4 — ncu capture target) ----
    agg_bf_kernel<64><<<aggBlocks, 256>>>(xbf, agg, n);                  // 4

    // ---- setup: zero out/gcnt + weight images ----
    {
        int total = G * 128 + G + 128 * 264 + 2 * (128 * 520);
        setup_kernel<<<(total + 255) / 256, 256>>>(Wl1, Wr1, Wl2, Wr2, Wl3, Wr3,
                                                   Bimg, out, G);        // 5
    }

    // ---- layer 1 GEMM (writes hA fp32 + hbf bf16) ----
    sage_mma<2, true, true><<<gemmGrid, 512, smem1>>>(agg, x, Bimg, bl1,
                                                      hA, hbf, n, nTiles);   // 6

    // ---- layer 2 ----
    agg_bf_kernel<128><<<aggBlocks, 256>>>(hbf, agg, n);                     // 7
    sage_mma<4, true, true><<<gemmGrid, 512, smem2>>>(agg, hA, Bimg + 33792, bl2,
                                                      hB, hbf, n, nTiles);   // 8

    // ---- layer 3 ----
    agg_bf_kernel<128><<<aggBlocks, 256>>>(hbf, agg, n);                     // 9
    sage_mma<4, false, false><<<gemmGrid, 512, smem2>>>(agg, hB, Bimg + 100352, bl3,
                                                        hA, hbf, n, nTiles); // 10

    // ---- global mean pool + restore deg/cursor invariant ----
    int poolWarps = (n + 15) / 16;
    pool_acc_kernel<<<(poolWarps * 32 + 255) / 256, 256>>>(hA, batch, out, n, G);  // 11
    pool_div_kernel<<<(n + 255) / 256, 256>>>(out, G, n);                          // 12
}

// round 15
// speedup vs baseline: 1.1312x; 1.1312x over previous
#include <cuda_runtime.h>
#include <cuda_bf16.h>
#include <cstdint>

// ---------------- problem constants ----------------
#define NMAX 50000
#define EMAX 600000
#define GMAX 256
#define DH 128

// ---------------- device scratch ----------------
// g_deg / g_cursor rely on static zero-init at load; pool_div restores them to
// zero at the end of every call, so the precondition holds for all replays.
__device__ float g_agg[(size_t)NMAX * DH];
__device__ float g_hA [(size_t)NMAX * DH];             // final layer fp32 output
__device__ unsigned short g_h1bf[(size_t)NMAX * DH];   // bf16 h after layer 1
__device__ unsigned short g_h2bf[(size_t)NMAX * DH];   // bf16 h after layer 2
__device__ int   g_deg[NMAX];
__device__ int   g_rowptr[NMAX + 1];
__device__ int   g_cursor[NMAX];
__device__ int   g_srcs[EMAX];
__device__ float g_gcnt[GMAX];
// pre-split bf16 hi/lo weight images, padded [n][2K+8] layout
__device__ unsigned short g_Bimg[167168];

__device__ __forceinline__ float bfbits2f_lo(uint32_t u) {
    return __uint_as_float(u << 16);
}
__device__ __forceinline__ float bfbits2f_hi(uint32_t u) {
    return __uint_as_float(u & 0xFFFF0000u);
}
__device__ __forceinline__ uint32_t pack_bf2(float x, float y) {
    __nv_bfloat16 hx = __float2bfloat16_rn(x);
    __nv_bfloat16 hy = __float2bfloat16_rn(y);
    return ((uint32_t)__bfloat16_as_ushort(hy) << 16) | __bfloat16_as_ushort(hx);
}

// ---------------- setup: zero out/gcnt + build 3 weight images ----------
__device__ __forceinline__ void prep_B_elem(const float* Wl, const float* Wr,
                                            unsigned short* img, int chunks, int t) {
    int strideB = chunks * 128 + 8;
    int Ktot    = chunks * 64;
    int nn = t / strideB;
    int kk = t - nn * strideB;
    if (kk < Ktot) {
        int half = chunks * 32;
        const float* W; int k;
        if (kk < half) { W = Wl; k = kk; } else { W = Wr; k = kk - half; }
        float v = W[(size_t)k * 128 + nn];
        __nv_bfloat16 h = __float2bfloat16_rn(v);
        __nv_bfloat16 l = __float2bfloat16_rn(v - __bfloat162float(h));
        img[nn * strideB + kk]        = __bfloat16_as_ushort(h);
        img[nn * strideB + Ktot + kk] = __bfloat16_as_ushort(l);
    } else if (kk >= 2 * Ktot) {
        img[t] = 0;
    }
}

__global__ void setup_kernel(const float* __restrict__ Wl1, const float* __restrict__ Wr1,
                             const float* __restrict__ Wl2, const float* __restrict__ Wr2,
                             const float* __restrict__ Wl3, const float* __restrict__ Wr3,
                             unsigned short* __restrict__ img,
                             float* __restrict__ out, int G) {
    const int s2 = G * 128;
    const int s3 = s2 + G;
    const int s4 = s3 + 128 * 264;
    const int s5 = s4 + 128 * 520;
    const int s6 = s5 + 128 * 520;
    for (int t = blockIdx.x * blockDim.x + threadIdx.x; t < s6;
         t += gridDim.x * blockDim.x) {
        if (t < s2)       out[t] = 0.0f;
        else if (t < s3)  g_gcnt[t - s2] = 0.0f;
        else if (t < s4)  prep_B_elem(Wl1, Wr1, img,          2, t - s3);
        else if (t < s5)  prep_B_elem(Wl2, Wr2, img + 33792,  4, t - s4);
        else              prep_B_elem(Wl3, Wr3, img + 100352, 4, t - s5);
    }
}

// ---------------- CSR build (4 edges/thread, int4 loads) ----------------
__global__ void count_deg_kernel(const int* __restrict__ dst, int E, int n) {
    int t = blockIdx.x * blockDim.x + threadIdx.x;
    int e = 4 * t;
    if (e + 3 < E) {
        int4 d4 = *(const int4*)(dst + e);
        if (d4.x >= 0 && d4.x < n) atomicAdd(&g_deg[d4.x], 1);
        if (d4.y >= 0 && d4.y < n) atomicAdd(&g_deg[d4.y], 1);
        if (d4.z >= 0 && d4.z < n) atomicAdd(&g_deg[d4.z], 1);
        if (d4.w >= 0 && d4.w < n) atomicAdd(&g_deg[d4.w], 1);
    } else {
        for (int k = 0; k < 4; k++) {
            int ee = e + k;
            if (ee < E) {
                int d = dst[ee];
                if (d >= 0 && d < n) atomicAdd(&g_deg[d], 1);
            }
        }
    }
}

__global__ void scan_kernel(int n) {
    __shared__ int sh[1024];
    int tid = threadIdx.x;
    int chunk = (n + 1023) / 1024;
    int beg = tid * chunk;
    int end = min(beg + chunk, n);
    int s = 0;
    for (int i = beg; i < end; i++) s += g_deg[i];
    sh[tid] = s;
    __syncthreads();
    for (int off = 1; off < 1024; off <<= 1) {
        int v = (tid >= off) ? sh[tid - off] : 0;
        __syncthreads();
        sh[tid] += v;
        __syncthreads();
    }
    int run = sh[tid] - s;
    for (int i = beg; i < end; i++) {
        g_rowptr[i] = run;
        g_cursor[i] = run;
        run += g_deg[i];
    }
    if (tid == 1023) g_rowptr[n] = sh[1023];
}

__global__ void scatter_kernel(const int* __restrict__ src,
                               const int* __restrict__ dst, int E, int n) {
    int t = blockIdx.x * blockDim.x + threadIdx.x;
    int e = 4 * t;
    if (e + 3 < E) {
        int4 s4 = *(const int4*)(src + e);
        int4 d4 = *(const int4*)(dst + e);
        int p;
        if (d4.x >= 0 && d4.x < n && s4.x >= 0 && s4.x < n) {
            p = atomicAdd(&g_cursor[d4.x], 1); if (p < EMAX) g_srcs[p] = s4.x;
        }
        if (d4.y >= 0 && d4.y < n && s4.y >= 0 && s4.y < n) {
            p = atomicAdd(&g_cursor[d4.y], 1); if (p < EMAX) g_srcs[p] = s4.y;
        }
        if (d4.z >= 0 && d4.z < n && s4.z >= 0 && s4.z < n) {
            p = atomicAdd(&g_cursor[d4.z], 1); if (p < EMAX) g_srcs[p] = s4.z;
        }
        if (d4.w >= 0 && d4.w < n && s4.w >= 0 && s4.w < n) {
            p = atomicAdd(&g_cursor[d4.w], 1); if (p < EMAX) g_srcs[p] = s4.w;
        }
    } else {
        for (int k = 0; k < 4; k++) {
            int ee = e + k;
            if (ee < E) {
                int d = dst[ee];
                int s = src[ee];
                if (d >= 0 && d < n && s >= 0 && s < n) {
                    int p = atomicAdd(&g_cursor[d], 1);
                    if (p < EMAX) g_srcs[p] = s;
                }
            }
        }
    }
}

// ---------------- fp32 mean aggregation (layer 1, D=64) ----------------
__global__ void agg_f32_kernel(const float* __restrict__ x, float* __restrict__ agg, int n) {
    const int D = 64;
    int gw   = (blockIdx.x * blockDim.x + threadIdx.x) >> 5;
    int lane = threadIdx.x & 31;
    if (gw >= n) return;
    int beg = g_rowptr[gw];
    int end = g_rowptr[gw + 1];
    float2 acc = make_float2(0.f, 0.f);
    int j = beg;
    for (; j + 3 < end; j += 4) {
        int s0 = g_srcs[j],     s1 = g_srcs[j + 1];
        int s2 = g_srcs[j + 2], s3 = g_srcs[j + 3];
        float2 v0 = __ldg((const float2*)(x + (size_t)s0 * D + 2 * lane));
        float2 v1 = __ldg((const float2*)(x + (size_t)s1 * D + 2 * lane));
        float2 v2 = __ldg((const float2*)(x + (size_t)s2 * D + 2 * lane));
        float2 v3 = __ldg((const float2*)(x + (size_t)s3 * D + 2 * lane));
        acc.x += (v0.x + v1.x) + (v2.x + v3.x);
        acc.y += (v0.y + v1.y) + (v2.y + v3.y);
    }
    for (; j < end; j++) {
        int s0 = g_srcs[j];
        float2 v0 = __ldg((const float2*)(x + (size_t)s0 * D + 2 * lane));
        acc.x += v0.x; acc.y += v0.y;
    }
    float inv = 1.0f / fmaxf((float)(end - beg), 1.0f);
    acc.x *= inv; acc.y *= inv;
    *(float2*)(agg + (size_t)gw * D + 2 * lane) = acc;
}

// ------- bf16 mean aggregation (layers 2/3, D=128), fp32 accumulate -------
__global__ void agg_bf_kernel(const unsigned short* __restrict__ xb,
                              float* __restrict__ agg, int n) {
    const int D = 128;
    int gw   = (blockIdx.x * blockDim.x + threadIdx.x) >> 5;
    int lane = threadIdx.x & 31;
    if (gw >= n) return;
    int beg = g_rowptr[gw];
    int end = g_rowptr[gw + 1];
    float4 acc = make_float4(0.f, 0.f, 0.f, 0.f);
    int j = beg;
    for (; j + 3 < end; j += 4) {
        int s0 = g_srcs[j],     s1 = g_srcs[j + 1];
        int s2 = g_srcs[j + 2], s3 = g_srcs[j + 3];
        uint2 u0 = __ldg((const uint2*)(xb + (size_t)s0 * D + 4 * lane));
        uint2 u1 = __ldg((const uint2*)(xb + (size_t)s1 * D + 4 * lane));
        uint2 u2 = __ldg((const uint2*)(xb + (size_t)s2 * D + 4 * lane));
        uint2 u3 = __ldg((const uint2*)(xb + (size_t)s3 * D + 4 * lane));
        acc.x += (bfbits2f_lo(u0.x) + bfbits2f_lo(u1.x)) + (bfbits2f_lo(u2.x) + bfbits2f_lo(u3.x));
        acc.y += (bfbits2f_hi(u0.x) + bfbits2f_hi(u1.x)) + (bfbits2f_hi(u2.x) + bfbits2f_hi(u3.x));
        acc.z += (bfbits2f_lo(u0.y) + bfbits2f_lo(u1.y)) + (bfbits2f_lo(u2.y) + bfbits2f_lo(u3.y));
        acc.w += (bfbits2f_hi(u0.y) + bfbits2f_hi(u1.y)) + (bfbits2f_hi(u2.y) + bfbits2f_hi(u3.y));
    }
    for (; j < end; j++) {
        int s0 = g_srcs[j];
        uint2 u0 = __ldg((const uint2*)(xb + (size_t)s0 * D + 4 * lane));
        acc.x += bfbits2f_lo(u0.x); acc.y += bfbits2f_hi(u0.x);
        acc.z += bfbits2f_lo(u0.y); acc.w += bfbits2f_hi(u0.y);
    }
    float inv = 1.0f / fmaxf((float)(end - beg), 1.0f);
    acc.x *= inv; acc.y *= inv; acc.z *= inv; acc.w *= inv;
    *(float4*)(agg + (size_t)gw * D + 4 * lane) = acc;
}

// ---------------- mma / ldmatrix helpers ----------------
__device__ __forceinline__ void mma16816(float* c, const uint32_t* a,
                                         uint32_t b0, uint32_t b1) {
    asm volatile(
        "mma.sync.aligned.m16n8k16.row.col.f32.bf16.bf16.f32 "
        "{%0,%1,%2,%3}, {%4,%5,%6,%7}, {%8,%9}, {%0,%1,%2,%3};"
        : "+f"(c[0]), "+f"(c[1]), "+f"(c[2]), "+f"(c[3])
        : "r"(a[0]), "r"(a[1]), "r"(a[2]), "r"(a[3]), "r"(b0), "r"(b1));
}

__device__ __forceinline__ void ldsm_x4(uint32_t* r, uint32_t addr) {
    asm volatile(
        "ldmatrix.sync.aligned.m8n8.x4.shared.b16 {%0,%1,%2,%3}, [%4];"
        : "=r"(r[0]), "=r"(r[1]), "=r"(r[2]), "=r"(r[3]) : "r"(addr));
}

__device__ __forceinline__ uint32_t smem_u32(const void* p) {
    uint32_t a;
    asm("{ .reg .u64 t; cvta.to.shared.u64 t, %1; cvt.u32.u64 %0, t; }"
        : "=r"(a) : "l"(p));
    return a;
}

// ---------------- persistent tensor-core fused SAGE GEMM ----------------
// out = [agg | h] @ [Wl;Wr] + b (+relu).
// agg chunks: fp32, 3-term split (Ah*Bh + Al*Bh + Ah*Bl).
// h chunks (A2BF): bf16 exact -> Al = 0, 2-term (Ah*Bh + Ah*Bl).
// OUTBF: write bf16 output only; else fp32 only.
// 512 threads, 16 warps (4m x 4n), warp tile 32x32, persistent grid=148.
template <int CHUNKS, bool RELU, bool A2BF, bool OUTBF>
__global__ __launch_bounds__(512, 1)
void sage_mma(const float* __restrict__ A1, const void* __restrict__ A2v,
              const unsigned short* __restrict__ Bimg, const float* __restrict__ bias,
              float* __restrict__ out, unsigned short* __restrict__ outbf,
              int n, int nTiles) {
    constexpr int STRIDEB = CHUNKS * 128 + 8;
    constexpr int KTOT    = CHUNKS * 64;
    constexpr int ASTRIDE = 136;
    constexpr int ASTR32  = CHUNKS * 32;   // row stride (fp32 elems / bf16 shorts)

    const float*          A2f = (const float*)A2v;
    const unsigned short* A2b = (const unsigned short*)A2v;

    extern __shared__ unsigned short sm[];
    unsigned short* As = sm;                    // 128 * 136
    unsigned short* Bs = sm + 128 * ASTRIDE;    // 128 * STRIDEB

    const int tid  = threadIdx.x;
    const int wid  = tid >> 5;
    const int lane = tid & 31;
    const int tq   = lane >> 2;
    const int tr   = lane & 3;
    const int wm   = wid & 3;
    const int wn   = wid >> 2;
    const int g    = lane >> 3;
    const int lr   = lane & 7;

    const uint32_t As_u = smem_u32(As);
    const uint32_t Bs_u = smem_u32(Bs);
    const uint32_t aBase = As_u + (uint32_t)(wm * 32 + (g & 1) * 8 + lr) * (ASTRIDE * 2)
                                + (uint32_t)((g >> 1) * 8) * 2;
    const uint32_t bBase = Bs_u + (uint32_t)(wn * 32 + (g >> 1) * 8 + lr) * (STRIDEB * 2)
                                + (uint32_t)((g & 1) * 8) * 2;

    {
        const float4* bsrc = (const float4*)Bimg;
        float4* bdst = (float4*)Bs;
        constexpr int NV = 128 * STRIDEB * 2 / 16;
        for (int i = tid; i < NV; i += 512) bdst[i] = bsrc[i];
    }

    const int lrow0 = tid >> 5;
    const int lk2   = (tid & 31) * 2;

    float2 v[8];
    auto load_chunk = [&](int m0, int c) {
        if (c < CHUNKS / 2) {
            int kb = c * 64;
#pragma unroll
            for (int i = 0; i < 8; i++) {
                int grow = min(m0 + lrow0 + 16 * i, n - 1);
                v[i] = *(const float2*)(A1 + (size_t)grow * ASTR32 + kb + lk2);
            }
        } else if (!A2BF) {
            int kb = (c - CHUNKS / 2) * 64;
#pragma unroll
            for (int i = 0; i < 8; i++) {
                int grow = min(m0 + lrow0 + 16 * i, n - 1);
                v[i] = *(const float2*)(A2f + (size_t)grow * ASTR32 + kb + lk2);
            }
        } else {
            int kb = (c - CHUNKS / 2) * 64;
#pragma unroll
            for (int i = 0; i < 8; i++) {
                int grow = min(m0 + lrow0 + 16 * i, n - 1);
                uint32_t u = *(const uint32_t*)(A2b + (size_t)grow * ASTR32 + kb + lk2);
                v[i].x = __uint_as_float(u);   // raw packed bf16 pair
            }
        }
    };

    int tile = blockIdx.x;
    if (tile < nTiles) load_chunk(tile * 128, 0);

    for (; tile < nTiles; tile += gridDim.x) {
        const int m0 = tile * 128;

        float acc[2][4][4];
#pragma unroll
        for (int a = 0; a < 2; a++)
#pragma unroll
            for (int b = 0; b < 4; b++)
#pragma unroll
                for (int q = 0; q < 4; q++) acc[a][b][q] = 0.0f;

        for (int c = 0; c < CHUNKS; ++c) {
            const bool isBF = A2BF && (c >= CHUNKS / 2);
            __syncthreads();

            // convert prefetched data -> hi/lo bf16 in smem
            if (isBF) {
#pragma unroll
                for (int i = 0; i < 8; i++) {
                    int row = lrow0 + 16 * i;
                    *(uint32_t*)(As + row * ASTRIDE + lk2)      = __float_as_uint(v[i].x);
                    *(uint32_t*)(As + row * ASTRIDE + 64 + lk2) = 0u;
                }
            } else {
#pragma unroll
                for (int i = 0; i < 8; i++) {
                    int row = lrow0 + 16 * i;
                    __nv_bfloat16 h0 = __float2bfloat16_rn(v[i].x);
                    __nv_bfloat16 h1 = __float2bfloat16_rn(v[i].y);
                    __nv_bfloat16 l0 = __float2bfloat16_rn(v[i].x - __bfloat162float(h0));
                    __nv_bfloat16 l1 = __float2bfloat16_rn(v[i].y - __bfloat162float(h1));
                    uint32_t hp = ((uint32_t)__bfloat16_as_ushort(h1) << 16) | __bfloat16_as_ushort(h0);
                    uint32_t lp = ((uint32_t)__bfloat16_as_ushort(l1) << 16) | __bfloat16_as_ushort(l0);
                    *(uint32_t*)(As + row * ASTRIDE + lk2)      = hp;
                    *(uint32_t*)(As + row * ASTRIDE + 64 + lk2) = lp;
                }
            }

            {
                int nc = c + 1, nt = tile;
                if (nc == CHUNKS) { nc = 0; nt = tile + gridDim.x; }
                if (nt < nTiles) load_chunk(nt * 128, nc);
            }
            __syncthreads();

#pragma unroll
            for (int ks = 0; ks < 4; ks++) {
                uint32_t ah[2][4], al[2][4], bh[2][4], bl[2][4];
#pragma unroll
                for (int ma = 0; ma < 2; ma++) {
                    uint32_t a = aBase + (uint32_t)(ma * 16 * ASTRIDE * 2 + ks * 32);
                    ldsm_x4(ah[ma], a);
                    if (!isBF) ldsm_x4(al[ma], a + 128);
                }
#pragma unroll
                for (int p = 0; p < 2; p++) {
                    uint32_t b = bBase + (uint32_t)(p * 16 * STRIDEB * 2 + c * 128 + ks * 32);
                    ldsm_x4(bh[p], b);
                    ldsm_x4(bl[p], b + KTOT * 2);
                }
#pragma unroll
                for (int pass = 0; pass < 3; pass++) {
                    if (pass == 1 && isBF) continue;   // Al == 0 for bf16 chunks
                    const uint32_t (*Af)[4] = (pass == 1) ? al : ah;
                    const uint32_t (*Bf)[4] = (pass == 2) ? bl : bh;
#pragma unroll
                    for (int ma = 0; ma < 2; ma++)
#pragma unroll
                        for (int p = 0; p < 2; p++) {
                            mma16816(acc[ma][2 * p],     Af[ma], Bf[p][0], Bf[p][1]);
                            mma16816(acc[ma][2 * p + 1], Af[ma], Bf[p][2], Bf[p][3]);
                        }
                }
            }
        }

#pragma unroll
        for (int ma = 0; ma < 2; ma++) {
            int row = m0 + wm * 32 + ma * 16 + tq;
#pragma unroll
            for (int nb = 0; nb < 4; nb++) {
                int col = wn * 32 + nb * 8 + 2 * tr;
                float2 bv = *(const float2*)(bias + col);
#pragma unroll
                for (int half = 0; half < 2; half++) {
                    int r = row + 8 * half;
                    if (r < n) {
                        float ox = acc[ma][nb][2 * half + 0] + bv.x;
                        float oy = acc[ma][nb][2 * half + 1] + bv.y;
                        if (RELU) { ox = fmaxf(ox, 0.0f); oy = fmaxf(oy, 0.0f); }
                        if (OUTBF) {
                            *(uint32_t*)(outbf + (size_t)r * 128 + col) = pack_bf2(ox, oy);
                        } else {
                            float2 o; o.x = ox; o.y = oy;
                            *(float2*)(out + (size_t)r * 128 + col) = o;
                        }
                    }
                }
            }
        }
    }
}

// ---------------- global mean pool ----------------
__global__ void pool_acc_kernel(const float* __restrict__ h,
                                const int* __restrict__ batch,
                                float* __restrict__ out, int n, int G) {
    const int NPW = 16;
    int gw   = (blockIdx.x * blockDim.x + threadIdx.x) >> 5;
    int lane = threadIdx.x & 31;
    int beg = gw * NPW;
    if (beg >= n) return;
    int end = min(beg + NPW, n);
    float a0 = 0, a1 = 0, a2 = 0, a3 = 0;
    int cur = min(max(batch[beg], 0), G - 1);
    int cnt = 0;
    for (int i = beg; i < end; i++) {
        int b = min(max(batch[i], 0), G - 1);
        if (b != cur) {
            atomicAdd(&out[cur * 128 + lane +  0], a0);
            atomicAdd(&out[cur * 128 + lane + 32], a1);
            atomicAdd(&out[cur * 128 + lane + 64], a2);
            atomicAdd(&out[cur * 128 + lane + 96], a3);
            if (lane == 0) atomicAdd(&g_gcnt[cur], (float)cnt);
            a0 = a1 = a2 = a3 = 0.0f;
            cnt = 0;
            cur = b;
        }
        const float* row = h + (size_t)i * 128;
        a0 += row[lane];      a1 += row[lane + 32];
        a2 += row[lane + 64]; a3 += row[lane + 96];
        cnt++;
    }
    atomicAdd(&out[cur * 128 + lane +  0], a0);
    atomicAdd(&out[cur * 128 + lane + 32], a1);
    atomicAdd(&out[cur * 128 + lane + 64], a2);
    atomicAdd(&out[cur * 128 + lane + 96], a3);
    if (lane == 0) atomicAdd(&g_gcnt[cur], (float)cnt);
}

// final: divide by counts AND restore g_deg/g_cursor to zero for next call
__global__ void pool_div_kernel(float* out, int G, int n) {
    int i = blockIdx.x * blockDim.x + threadIdx.x;
    if (i < G * 128) out[i] /= fmaxf(g_gcnt[i >> 7], 1.0f);
    if (i < n) { g_deg[i] = 0; g_cursor[i] = 0; }
}

// ---------------- launch ----------------
extern "C" void kernel_launch(void* const* d_in, const int* in_sizes, int n_in,
                              void* d_out, int out_size) {
    const float* x     = (const float*)d_in[0];
    const int*   ei    = (const int*)d_in[1];
    const int*   batch = (const int*)d_in[2];
    const float* Wl1 = (const float*)d_in[3];
    const float* bl1 = (const float*)d_in[4];
    const float* Wr1 = (const float*)d_in[5];
    const float* Wl2 = (const float*)d_in[6];
    const float* bl2 = (const float*)d_in[7];
    const float* Wr2 = (const float*)d_in[8];
    const float* Wl3 = (const float*)d_in[9];
    const float* bl3 = (const float*)d_in[10];
    const float* Wr3 = (const float*)d_in[11];
    float* out = (float*)d_out;

    const int n = in_sizes[0] / 64;       // 50000
    const int E = in_sizes[1] / 2;        // 600000
    const int G = out_size / 128;         // 64

    const int* src = ei;
    const int* dst = ei + E;

    void *p_agg, *p_hA, *p_Bimg, *p_h1, *p_h2;
    cudaGetSymbolAddress(&p_agg, g_agg);
    cudaGetSymbolAddress(&p_hA, g_hA);
    cudaGetSymbolAddress(&p_Bimg, g_Bimg);
    cudaGetSymbolAddress(&p_h1, g_h1bf);
    cudaGetSymbolAddress(&p_h2, g_h2bf);
    float* agg = (float*)p_agg;
    float* hA  = (float*)p_hA;
    unsigned short* Bimg = (unsigned short*)p_Bimg;
    unsigned short* h1bf = (unsigned short*)p_h1;
    unsigned short* h2bf = (unsigned short*)p_h2;

    const int smem1 = (128 * 136 + 128 * 264) * 2;   // 102400 (CHUNKS=2)
    const int smem2 = (128 * 136 + 128 * 520) * 2;   // 167936 (CHUNKS=4)
    cudaFuncSetAttribute(sage_mma<2, true,  false, true >, cudaFuncAttributeMaxDynamicSharedMemorySize, smem1);
    cudaFuncSetAttribute(sage_mma<4, true,  true,  true >, cudaFuncAttributeMaxDynamicSharedMemorySize, smem2);
    cudaFuncSetAttribute(sage_mma<4, false, true,  false>, cudaFuncAttributeMaxDynamicSharedMemorySize, smem2);

    const int aggBlocks = (n * 32 + 255) / 256;
    const int nTiles = (n + 127) / 128;
    const int gemmGrid = 148;
    int quads = (E + 3) / 4;

    // ---- CSR build (g_deg/g_cursor zero by invariant) ----
    count_deg_kernel<<<(quads + 255) / 256, 256>>>(dst, E, n);        // 1
    scan_kernel<<<1, 1024>>>(n);                                       // 2
    scatter_kernel<<<(quads + 255) / 256, 256>>>(src, dst, E, n);      // 3

    // ---- agg layer 1 fp32 (launch #4 — ncu capture target) ----
    agg_f32_kernel<<<aggBlocks, 256>>>(x, agg, n);                     // 4

    // ---- setup: zero out/gcnt + weight images ----
    {
        int total = G * 128 + G + 128 * 264 + 2 * (128 * 520);
        setup_kernel<<<(total + 255) / 256, 256>>>(Wl1, Wr1, Wl2, Wr2, Wl3, Wr3,
                                                   Bimg, out, G);      // 5
    }

    // ---- layer 1 GEMM: fp32 inputs -> bf16 h1 ----
    sage_mma<2, true, false, true><<<gemmGrid, 512, smem1>>>(
        agg, x, Bimg, bl1, hA, h1bf, n, nTiles);                       // 6

    // ---- layer 2: bf16 h1 -> bf16 h2 ----
    agg_bf_kernel<<<aggBlocks, 256>>>(h1bf, agg, n);                   // 7
    sage_mma<4, true, true, true><<<gemmGrid, 512, smem2>>>(
        agg, h1bf, Bimg + 33792, bl2, hA, h2bf, n, nTiles);            // 8

    // ---- layer 3: bf16 h2 -> fp32 h3 ----
    agg_bf_kernel<<<aggBlocks, 256>>>(h2bf, agg, n);                   // 9
    sage_mma<4, false, true, false><<<gemmGrid, 512, smem2>>>(
        agg, h2bf, Bimg + 100352, bl3, hA, h1bf, n, nTiles);           // 10

    // ---- global mean pool + restore deg/cursor invariant ----
    int poolWarps = (n + 15) / 16;
    pool_acc_kernel<<<(poolWarps * 32 + 255) / 256, 256>>>(hA, batch, out, n, G);  // 11
    pool_div_kernel<<<(n + 255) / 256, 256>>>(out, G, n);                          // 12
}

// round 16
// speedup vs baseline: 1.2072x; 1.0672x over previous
#include <cuda_runtime.h>
#include <cuda_bf16.h>
#include <cstdint>

// ---------------- problem constants ----------------
#define NMAX 50000
#define EMAX 600000
#define GMAX 256
#define DH 128

// ---------------- device scratch ----------------
// g_deg / g_cursor rely on static zero-init at load; pool_div restores them to
// zero at the end of every call, so the precondition holds for all replays.
__device__ float g_agg[(size_t)NMAX * DH];             // fp32 agg (L1) / bf16 agg (L2,3 via cast)
__device__ float g_hA [(size_t)NMAX * DH];             // final layer fp32 output
__device__ unsigned short g_h1bf[(size_t)NMAX * DH];   // bf16 h after layer 1
__device__ unsigned short g_h2bf[(size_t)NMAX * DH];   // bf16 h after layer 2
__device__ int   g_deg[NMAX];
__device__ int   g_rowptr[NMAX + 1];
__device__ int   g_cursor[NMAX];
__device__ int   g_srcs[EMAX];
__device__ float g_gcnt[GMAX];
// pre-split bf16 hi/lo weight images, padded [n][2K+8] layout
__device__ unsigned short g_Bimg[167168];

__device__ __forceinline__ float bfbits2f_lo(uint32_t u) {
    return __uint_as_float(u << 16);
}
__device__ __forceinline__ float bfbits2f_hi(uint32_t u) {
    return __uint_as_float(u & 0xFFFF0000u);
}
__device__ __forceinline__ uint32_t pack_bf2(float x, float y) {
    __nv_bfloat16 hx = __float2bfloat16_rn(x);
    __nv_bfloat16 hy = __float2bfloat16_rn(y);
    return ((uint32_t)__bfloat16_as_ushort(hy) << 16) | __bfloat16_as_ushort(hx);
}

// ---------------- setup: zero out/gcnt + build 3 weight images ----------
__device__ __forceinline__ void prep_B_elem(const float* Wl, const float* Wr,
                                            unsigned short* img, int chunks, int t) {
    int strideB = chunks * 128 + 8;
    int Ktot    = chunks * 64;
    int nn = t / strideB;
    int kk = t - nn * strideB;
    if (kk < Ktot) {
        int half = chunks * 32;
        const float* W; int k;
        if (kk < half) { W = Wl; k = kk; } else { W = Wr; k = kk - half; }
        float v = W[(size_t)k * 128 + nn];
        __nv_bfloat16 h = __float2bfloat16_rn(v);
        __nv_bfloat16 l = __float2bfloat16_rn(v - __bfloat162float(h));
        img[nn * strideB + kk]        = __bfloat16_as_ushort(h);
        img[nn * strideB + Ktot + kk] = __bfloat16_as_ushort(l);
    } else if (kk >= 2 * Ktot) {
        img[t] = 0;
    }
}

__global__ void setup_kernel(const float* __restrict__ Wl1, const float* __restrict__ Wr1,
                             const float* __restrict__ Wl2, const float* __restrict__ Wr2,
                             const float* __restrict__ Wl3, const float* __restrict__ Wr3,
                             unsigned short* __restrict__ img,
                             float* __restrict__ out, int G) {
    const int s2 = G * 128;
    const int s3 = s2 + G;
    const int s4 = s3 + 128 * 264;
    const int s5 = s4 + 128 * 520;
    const int s6 = s5 + 128 * 520;
    for (int t = blockIdx.x * blockDim.x + threadIdx.x; t < s6;
         t += gridDim.x * blockDim.x) {
        if (t < s2)       out[t] = 0.0f;
        else if (t < s3)  g_gcnt[t - s2] = 0.0f;
        else if (t < s4)  prep_B_elem(Wl1, Wr1, img,          2, t - s3);
        else if (t < s5)  prep_B_elem(Wl2, Wr2, img + 33792,  4, t - s4);
        else              prep_B_elem(Wl3, Wr3, img + 100352, 4, t - s5);
    }
}

// ---------------- CSR build (4 edges/thread, int4 loads) ----------------
__global__ void count_deg_kernel(const int* __restrict__ dst, int E, int n) {
    int t = blockIdx.x * blockDim.x + threadIdx.x;
    int e = 4 * t;
    if (e + 3 < E) {
        int4 d4 = *(const int4*)(dst + e);
        if (d4.x >= 0 && d4.x < n) atomicAdd(&g_deg[d4.x], 1);
        if (d4.y >= 0 && d4.y < n) atomicAdd(&g_deg[d4.y], 1);
        if (d4.z >= 0 && d4.z < n) atomicAdd(&g_deg[d4.z], 1);
        if (d4.w >= 0 && d4.w < n) atomicAdd(&g_deg[d4.w], 1);
    } else {
        for (int k = 0; k < 4; k++) {
            int ee = e + k;
            if (ee < E) {
                int d = dst[ee];
                if (d >= 0 && d < n) atomicAdd(&g_deg[d], 1);
            }
        }
    }
}

__global__ void scan_kernel(int n) {
    __shared__ int sh[1024];
    int tid = threadIdx.x;
    int chunk = (n + 1023) / 1024;
    int beg = tid * chunk;
    int end = min(beg + chunk, n);
    int s = 0;
    for (int i = beg; i < end; i++) s += g_deg[i];
    sh[tid] = s;
    __syncthreads();
    for (int off = 1; off < 1024; off <<= 1) {
        int v = (tid >= off) ? sh[tid - off] : 0;
        __syncthreads();
        sh[tid] += v;
        __syncthreads();
    }
    int run = sh[tid] - s;
    for (int i = beg; i < end; i++) {
        g_rowptr[i] = run;
        g_cursor[i] = run;
        run += g_deg[i];
    }
    if (tid == 1023) g_rowptr[n] = sh[1023];
}

__global__ void scatter_kernel(const int* __restrict__ src,
                               const int* __restrict__ dst, int E, int n) {
    int t = blockIdx.x * blockDim.x + threadIdx.x;
    int e = 4 * t;
    if (e + 3 < E) {
        int4 s4 = *(const int4*)(src + e);
        int4 d4 = *(const int4*)(dst + e);
        int p;
        if (d4.x >= 0 && d4.x < n && s4.x >= 0 && s4.x < n) {
            p = atomicAdd(&g_cursor[d4.x], 1); if (p < EMAX) g_srcs[p] = s4.x;
        }
        if (d4.y >= 0 && d4.y < n && s4.y >= 0 && s4.y < n) {
            p = atomicAdd(&g_cursor[d4.y], 1); if (p < EMAX) g_srcs[p] = s4.y;
        }
        if (d4.z >= 0 && d4.z < n && s4.z >= 0 && s4.z < n) {
            p = atomicAdd(&g_cursor[d4.z], 1); if (p < EMAX) g_srcs[p] = s4.z;
        }
        if (d4.w >= 0 && d4.w < n && s4.w >= 0 && s4.w < n) {
            p = atomicAdd(&g_cursor[d4.w], 1); if (p < EMAX) g_srcs[p] = s4.w;
        }
    } else {
        for (int k = 0; k < 4; k++) {
            int ee = e + k;
            if (ee < E) {
                int d = dst[ee];
                int s = src[ee];
                if (d >= 0 && d < n && s >= 0 && s < n) {
                    int p = atomicAdd(&g_cursor[d], 1);
                    if (p < EMAX) g_srcs[p] = s;
                }
            }
        }
    }
}

// ---------------- fp32 mean aggregation (layer 1, D=64) ----------------
__global__ void agg_f32_kernel(const float* __restrict__ x, float* __restrict__ agg, int n) {
    const int D = 64;
    int gw   = (blockIdx.x * blockDim.x + threadIdx.x) >> 5;
    int lane = threadIdx.x & 31;
    if (gw >= n) return;
    int beg = g_rowptr[gw];
    int end = g_rowptr[gw + 1];
    float2 acc = make_float2(0.f, 0.f);
    int j = beg;
    for (; j + 3 < end; j += 4) {
        int s0 = g_srcs[j],     s1 = g_srcs[j + 1];
        int s2 = g_srcs[j + 2], s3 = g_srcs[j + 3];
        float2 v0 = __ldg((const float2*)(x + (size_t)s0 * D + 2 * lane));
        float2 v1 = __ldg((const float2*)(x + (size_t)s1 * D + 2 * lane));
        float2 v2 = __ldg((const float2*)(x + (size_t)s2 * D + 2 * lane));
        float2 v3 = __ldg((const float2*)(x + (size_t)s3 * D + 2 * lane));
        acc.x += (v0.x + v1.x) + (v2.x + v3.x);
        acc.y += (v0.y + v1.y) + (v2.y + v3.y);
    }
    for (; j < end; j++) {
        int s0 = g_srcs[j];
        float2 v0 = __ldg((const float2*)(x + (size_t)s0 * D + 2 * lane));
        acc.x += v0.x; acc.y += v0.y;
    }
    float inv = 1.0f / fmaxf((float)(end - beg), 1.0f);
    acc.x *= inv; acc.y *= inv;
    *(float2*)(agg + (size_t)gw * D + 2 * lane) = acc;
}

// -- bf16 mean aggregation (layers 2/3, D=128), fp32 accumulate, bf16 out --
__global__ void agg_bf_kernel(const unsigned short* __restrict__ xb,
                              unsigned short* __restrict__ aggb, int n) {
    const int D = 128;
    int gw   = (blockIdx.x * blockDim.x + threadIdx.x) >> 5;
    int lane = threadIdx.x & 31;
    if (gw >= n) return;
    int beg = g_rowptr[gw];
    int end = g_rowptr[gw + 1];
    float4 acc = make_float4(0.f, 0.f, 0.f, 0.f);
    int j = beg;
    for (; j + 3 < end; j += 4) {
        int s0 = g_srcs[j],     s1 = g_srcs[j + 1];
        int s2 = g_srcs[j + 2], s3 = g_srcs[j + 3];
        uint2 u0 = __ldg((const uint2*)(xb + (size_t)s0 * D + 4 * lane));
        uint2 u1 = __ldg((const uint2*)(xb + (size_t)s1 * D + 4 * lane));
        uint2 u2 = __ldg((const uint2*)(xb + (size_t)s2 * D + 4 * lane));
        uint2 u3 = __ldg((const uint2*)(xb + (size_t)s3 * D + 4 * lane));
        acc.x += (bfbits2f_lo(u0.x) + bfbits2f_lo(u1.x)) + (bfbits2f_lo(u2.x) + bfbits2f_lo(u3.x));
        acc.y += (bfbits2f_hi(u0.x) + bfbits2f_hi(u1.x)) + (bfbits2f_hi(u2.x) + bfbits2f_hi(u3.x));
        acc.z += (bfbits2f_lo(u0.y) + bfbits2f_lo(u1.y)) + (bfbits2f_lo(u2.y) + bfbits2f_lo(u3.y));
        acc.w += (bfbits2f_hi(u0.y) + bfbits2f_hi(u1.y)) + (bfbits2f_hi(u2.y) + bfbits2f_hi(u3.y));
    }
    for (; j < end; j++) {
        int s0 = g_srcs[j];
        uint2 u0 = __ldg((const uint2*)(xb + (size_t)s0 * D + 4 * lane));
        acc.x += bfbits2f_lo(u0.x); acc.y += bfbits2f_hi(u0.x);
        acc.z += bfbits2f_lo(u0.y); acc.w += bfbits2f_hi(u0.y);
    }
    float inv = 1.0f / fmaxf((float)(end - beg), 1.0f);
    uint2 o;
    o.x = pack_bf2(acc.x * inv, acc.y * inv);
    o.y = pack_bf2(acc.z * inv, acc.w * inv);
    *(uint2*)(aggb + (size_t)gw * D + 4 * lane) = o;
}

// ---------------- mma / ldmatrix helpers ----------------
__device__ __forceinline__ void mma16816(float* c, const uint32_t* a,
                                         uint32_t b0, uint32_t b1) {
    asm volatile(
        "mma.sync.aligned.m16n8k16.row.col.f32.bf16.bf16.f32 "
        "{%0,%1,%2,%3}, {%4,%5,%6,%7}, {%8,%9}, {%0,%1,%2,%3};"
        : "+f"(c[0]), "+f"(c[1]), "+f"(c[2]), "+f"(c[3])
        : "r"(a[0]), "r"(a[1]), "r"(a[2]), "r"(a[3]), "r"(b0), "r"(b1));
}

__device__ __forceinline__ void ldsm_x4(uint32_t* r, uint32_t addr) {
    asm volatile(
        "ldmatrix.sync.aligned.m8n8.x4.shared.b16 {%0,%1,%2,%3}, [%4];"
        : "=r"(r[0]), "=r"(r[1]), "=r"(r[2]), "=r"(r[3]) : "r"(addr));
}

__device__ __forceinline__ uint32_t smem_u32(const void* p) {
    uint32_t a;
    asm("{ .reg .u64 t; cvta.to.shared.u64 t, %1; cvt.u32.u64 %0, t; }"
        : "=r"(a) : "l"(p));
    return a;
}

// ---------------- persistent tensor-core fused SAGE GEMM ----------------
// out = [agg | h] @ [Wl;Wr] + b (+relu).
// ABF=false (layer 1): A1/A2 fp32, 3-term split (Ah*Bh + Al*Bh + Ah*Bl).
// ABF=true (layers 2/3): A1/A2 bf16 exact -> Al = 0, 2-term (Ah*Bh + Ah*Bl).
// OUTBF: write bf16 output only; else fp32 only.
// 512 threads, 16 warps (4m x 4n), warp tile 32x32, persistent grid=148.
template <int CHUNKS, bool RELU, bool ABF, bool OUTBF>
__global__ __launch_bounds__(512, 1)
void sage_mma(const void* __restrict__ A1v, const void* __restrict__ A2v,
              const unsigned short* __restrict__ Bimg, const float* __restrict__ bias,
              float* __restrict__ out, unsigned short* __restrict__ outbf,
              int n, int nTiles) {
    constexpr int STRIDEB = CHUNKS * 128 + 8;
    constexpr int KTOT    = CHUNKS * 64;
    constexpr int ASTRIDE = 136;
    constexpr int ASTR    = CHUNKS * 32;   // row stride (fp32 elems or bf16 shorts x2)

    const float*          A1f = (const float*)A1v;
    const float*          A2f = (const float*)A2v;
    const unsigned short* A1b = (const unsigned short*)A1v;
    const unsigned short* A2b = (const unsigned short*)A2v;

    extern __shared__ unsigned short sm[];
    unsigned short* As = sm;                    // 128 * 136
    unsigned short* Bs = sm + 128 * ASTRIDE;    // 128 * STRIDEB

    const int tid  = threadIdx.x;
    const int wid  = tid >> 5;
    const int lane = tid & 31;
    const int tq   = lane >> 2;
    const int tr   = lane & 3;
    const int wm   = wid & 3;
    const int wn   = wid >> 2;
    const int g    = lane >> 3;
    const int lr   = lane & 7;

    const uint32_t As_u = smem_u32(As);
    const uint32_t Bs_u = smem_u32(Bs);
    const uint32_t aBase = As_u + (uint32_t)(wm * 32 + (g & 1) * 8 + lr) * (ASTRIDE * 2)
                                + (uint32_t)((g >> 1) * 8) * 2;
    const uint32_t bBase = Bs_u + (uint32_t)(wn * 32 + (g >> 1) * 8 + lr) * (STRIDEB * 2)
                                + (uint32_t)((g & 1) * 8) * 2;

    {
        const float4* bsrc = (const float4*)Bimg;
        float4* bdst = (float4*)Bs;
        constexpr int NV = 128 * STRIDEB * 2 / 16;
        for (int i = tid; i < NV; i += 512) bdst[i] = bsrc[i];
    }

    const int lrow0 = tid >> 5;
    const int lk2   = (tid & 31) * 2;

    float2 v[8];
    auto load_chunk = [&](int m0, int c) {
        const bool first = (c < CHUNKS / 2);
        int kb = (first ? c : (c - CHUNKS / 2)) * 64;
        if (!ABF) {
            const float* src = first ? A1f : A2f;
#pragma unroll
            for (int i = 0; i < 8; i++) {
                int grow = min(m0 + lrow0 + 16 * i, n - 1);
                v[i] = *(const float2*)(src + (size_t)grow * ASTR + kb + lk2);
            }
        } else {
            // bf16 rows: ASTR shorts per... row stride = CHUNKS*64 shorts? No:
            // full concat row is CHUNKS*64 bf16 per source (each source D = CHUNKS/2*64
            // fp32-equiv cols = CHUNKS*32 pairs). Row stride in shorts = CHUNKS*32*2? 
            // For CHUNKS=4: D=128 shorts per row. kb in shorts, lk2 in shorts.
            const unsigned short* src = first ? A1b : A2b;
#pragma unroll
            for (int i = 0; i < 8; i++) {
                int grow = min(m0 + lrow0 + 16 * i, n - 1);
                uint32_t u = *(const uint32_t*)(src + (size_t)grow * (CHUNKS * 32) + kb + lk2);
                v[i].x = __uint_as_float(u);
            }
        }
    };

    int tile = blockIdx.x;
    if (tile < nTiles) load_chunk(tile * 128, 0);

    for (; tile < nTiles; tile += gridDim.x) {
        const int m0 = tile * 128;

        float acc[2][4][4];
#pragma unroll
        for (int a = 0; a < 2; a++)
#pragma unroll
            for (int b = 0; b < 4; b++)
#pragma unroll
                for (int q = 0; q < 4; q++) acc[a][b][q] = 0.0f;

        for (int c = 0; c < CHUNKS; ++c) {
            __syncthreads();

            if (ABF) {
#pragma unroll
                for (int i = 0; i < 8; i++) {
                    int row = lrow0 + 16 * i;
                    *(uint32_t*)(As + row * ASTRIDE + lk2) = __float_as_uint(v[i].x);
                }
            } else {
#pragma unroll
                for (int i = 0; i < 8; i++) {
                    int row = lrow0 + 16 * i;
                    __nv_bfloat16 h0 = __float2bfloat16_rn(v[i].x);
                    __nv_bfloat16 h1 = __float2bfloat16_rn(v[i].y);
                    __nv_bfloat16 l0 = __float2bfloat16_rn(v[i].x - __bfloat162float(h0));
                    __nv_bfloat16 l1 = __float2bfloat16_rn(v[i].y - __bfloat162float(h1));
                    uint32_t hp = ((uint32_t)__bfloat16_as_ushort(h1) << 16) | __bfloat16_as_ushort(h0);
                    uint32_t lp = ((uint32_t)__bfloat16_as_ushort(l1) << 16) | __bfloat16_as_ushort(l0);
                    *(uint32_t*)(As + row * ASTRIDE + lk2)      = hp;
                    *(uint32_t*)(As + row * ASTRIDE + 64 + lk2) = lp;
                }
            }

            {
                int nc = c + 1, nt = tile;
                if (nc == CHUNKS) { nc = 0; nt = tile + gridDim.x; }
                if (nt < nTiles) load_chunk(nt * 128, nc);
            }
            __syncthreads();

#pragma unroll
            for (int ks = 0; ks < 4; ks++) {
                uint32_t ah[2][4], al[2][4], bh[2][4], bl[2][4];
#pragma unroll
                for (int ma = 0; ma < 2; ma++) {
                    uint32_t a = aBase + (uint32_t)(ma * 16 * ASTRIDE * 2 + ks * 32);
                    ldsm_x4(ah[ma], a);
                    if (!ABF) ldsm_x4(al[ma], a + 128);
                }
#pragma unroll
                for (int p = 0; p < 2; p++) {
                    uint32_t b = bBase + (uint32_t)(p * 16 * STRIDEB * 2 + c * 128 + ks * 32);
                    ldsm_x4(bh[p], b);
                    ldsm_x4(bl[p], b + KTOT * 2);
                }
#pragma unroll
                for (int pass = 0; pass < 3; pass++) {
                    if (pass == 1 && ABF) continue;   // Al == 0 for bf16 A
                    const uint32_t (*Af)[4] = (pass == 1) ? al : ah;
                    const uint32_t (*Bf)[4] = (pass == 2) ? bl : bh;
#pragma unroll
                    for (int ma = 0; ma < 2; ma++)
#pragma unroll
                        for (int p = 0; p < 2; p++) {
                            mma16816(acc[ma][2 * p],     Af[ma], Bf[p][0], Bf[p][1]);
                            mma16816(acc[ma][2 * p + 1], Af[ma], Bf[p][2], Bf[p][3]);
                        }
                }
            }
        }

#pragma unroll
        for (int ma = 0; ma < 2; ma++) {
            int row = m0 + wm * 32 + ma * 16 + tq;
#pragma unroll
            for (int nb = 0; nb < 4; nb++) {
                int col = wn * 32 + nb * 8 + 2 * tr;
                float2 bv = *(const float2*)(bias + col);
#pragma unroll
                for (int half = 0; half < 2; half++) {
                    int r = row + 8 * half;
                    if (r < n) {
                        float ox = acc[ma][nb][2 * half + 0] + bv.x;
                        float oy = acc[ma][nb][2 * half + 1] + bv.y;
                        if (RELU) { ox = fmaxf(ox, 0.0f); oy = fmaxf(oy, 0.0f); }
                        if (OUTBF) {
                            *(uint32_t*)(outbf + (size_t)r * 128 + col) = pack_bf2(ox, oy);
                        } else {
                            float2 o; o.x = ox; o.y = oy;
                            *(float2*)(out + (size_t)r * 128 + col) = o;
                        }
                    }
                }
            }
        }
    }
}

// ---------------- global mean pool ----------------
__global__ void pool_acc_kernel(const float* __restrict__ h,
                                const int* __restrict__ batch,
                                float* __restrict__ out, int n, int G) {
    const int NPW = 16;
    int gw   = (blockIdx.x * blockDim.x + threadIdx.x) >> 5;
    int lane = threadIdx.x & 31;
    int beg = gw * NPW;
    if (beg >= n) return;
    int end = min(beg + NPW, n);
    float a0 = 0, a1 = 0, a2 = 0, a3 = 0;
    int cur = min(max(batch[beg], 0), G - 1);
    int cnt = 0;
    for (int i = beg; i < end; i++) {
        int b = min(max(batch[i], 0), G - 1);
        if (b != cur) {
            atomicAdd(&out[cur * 128 + lane +  0], a0);
            atomicAdd(&out[cur * 128 + lane + 32], a1);
            atomicAdd(&out[cur * 128 + lane + 64], a2);
            atomicAdd(&out[cur * 128 + lane + 96], a3);
            if (lane == 0) atomicAdd(&g_gcnt[cur], (float)cnt);
            a0 = a1 = a2 = a3 = 0.0f;
            cnt = 0;
            cur = b;
        }
        const float* row = h + (size_t)i * 128;
        a0 += row[lane];      a1 += row[lane + 32];
        a2 += row[lane + 64]; a3 += row[lane + 96];
        cnt++;
    }
    atomicAdd(&out[cur * 128 + lane +  0], a0);
    atomicAdd(&out[cur * 128 + lane + 32], a1);
    atomicAdd(&out[cur * 128 + lane + 64], a2);
    atomicAdd(&out[cur * 128 + lane + 96], a3);
    if (lane == 0) atomicAdd(&g_gcnt[cur], (float)cnt);
}

// final: divide by counts AND restore g_deg/g_cursor to zero for next call
__global__ void pool_div_kernel(float* out, int G, int n) {
    int i = blockIdx.x * blockDim.x + threadIdx.x;
    if (i < G * 128) out[i] /= fmaxf(g_gcnt[i >> 7], 1.0f);
    if (i < n) { g_deg[i] = 0; g_cursor[i] = 0; }
}

// ---------------- launch ----------------
extern "C" void kernel_launch(void* const* d_in, const int* in_sizes, int n_in,
                              void* d_out, int out_size) {
    const float* x     = (const float*)d_in[0];
    const int*   ei    = (const int*)d_in[1];
    const int*   batch = (const int*)d_in[2];
    const float* Wl1 = (const float*)d_in[3];
    const float* bl1 = (const float*)d_in[4];
    const float* Wr1 = (const float*)d_in[5];
    const float* Wl2 = (const float*)d_in[6];
    const float* bl2 = (const float*)d_in[7];
    const float* Wr2 = (const float*)d_in[8];
    const float* Wl3 = (const float*)d_in[9];
    const float* bl3 = (const float*)d_in[10];
    const float* Wr3 = (const float*)d_in[11];
    float* out = (float*)d_out;

    const int n = in_sizes[0] / 64;       // 50000
    const int E = in_sizes[1] / 2;        // 600000
    const int G = out_size / 128;         // 64

    const int* src = ei;
    const int* dst = ei + E;

    void *p_agg, *p_hA, *p_Bimg, *p_h1, *p_h2;
    cudaGetSymbolAddress(&p_agg, g_agg);
    cudaGetSymbolAddress(&p_hA, g_hA);
    cudaGetSymbolAddress(&p_Bimg, g_Bimg);
    cudaGetSymbolAddress(&p_h1, g_h1bf);
    cudaGetSymbolAddress(&p_h2, g_h2bf);
    float* aggf = (float*)p_agg;
    unsigned short* aggb = (unsigned short*)p_agg;   // reuse as bf16 agg
    float* hA  = (float*)p_hA;
    unsigned short* Bimg = (unsigned short*)p_Bimg;
    unsigned short* h1bf = (unsigned short*)p_h1;
    unsigned short* h2bf = (unsigned short*)p_h2;

    const int smem1 = (128 * 136 + 128 * 264) * 2;   // 102400 (CHUNKS=2)
    const int smem2 = (128 * 136 + 128 * 520) * 2;   // 167936 (CHUNKS=4)
    cudaFuncSetAttribute(sage_mma<2, true,  false, true >, cudaFuncAttributeMaxDynamicSharedMemorySize, smem1);
    cudaFuncSetAttribute(sage_mma<4, true,  true,  true >, cudaFuncAttributeMaxDynamicSharedMemorySize, smem2);
    cudaFuncSetAttribute(sage_mma<4, false, true,  false>, cudaFuncAttributeMaxDynamicSharedMemorySize, smem2);

    const int aggBlocks = (n * 32 + 255) / 256;
    const int nTiles = (n + 127) / 128;
    const int gemmGrid = 148;
    int quads = (E + 3) / 4;

    // ---- CSR build (g_deg/g_cursor zero by invariant) ----
    count_deg_kernel<<<(quads + 255) / 256, 256>>>(dst, E, n);        // 1
    scan_kernel<<<1, 1024>>>(n);                                       // 2
    scatter_kernel<<<(quads + 255) / 256, 256>>>(src, dst, E, n);      // 3

    // ---- agg layer 1 fp32 (launch #4 — ncu capture target) ----
    agg_f32_kernel<<<aggBlocks, 256>>>(x, aggf, n);                    // 4

    // ---- setup: zero out/gcnt + weight images ----
    {
        int total = G * 128 + G + 128 * 264 + 2 * (128 * 520);
        setup_kernel<<<(total + 255) / 256, 256>>>(Wl1, Wr1, Wl2, Wr2, Wl3, Wr3,
                                                   Bimg, out, G);      // 5
    }

    // ---- layer 1 GEMM: fp32 inputs (3-term) -> bf16 h1 ----
    sage_mma<2, true, false, true><<<gemmGrid, 512, smem1>>>(
        aggf, x, Bimg, bl1, hA, h1bf, n, nTiles);                      // 6

    // ---- layer 2: all-bf16 A (2-term) -> bf16 h2 ----
    agg_bf_kernel<<<aggBlocks, 256>>>(h1bf, aggb, n);                  // 7
    sage_mma<4, true, true, true><<<gemmGrid, 512, smem2>>>(
        aggb, h1bf, Bimg + 33792, bl2, hA, h2bf, n, nTiles);           // 8

    // ---- layer 3: all-bf16 A (2-term) -> fp32 h3 ----
    agg_bf_kernel<<<aggBlocks, 256>>>(h2bf, aggb, n);                  // 9
    sage_mma<4, false, true, false><<<gemmGrid, 512, smem2>>>(
        aggb, h2bf, Bimg + 100352, bl3, hA, h1bf, n, nTiles);          // 10

    // ---- global mean pool + restore deg/cursor invariant ----
    int poolWarps = (n + 15) / 16;
    pool_acc_kernel<<<(poolWarps * 32 + 255) / 256, 256>>>(hA, batch, out, n, G);  // 11
    pool_div_kernel<<<(n + 255) / 256, 256>>>(out, G, n);                          // 12
}